// round 11
// baseline (speedup 1.0000x reference)
#include <cuda_runtime.h>
#include <cuda_fp16.h>

// LocalPosEnc2D: bilinear grid sample (513x513 x 24ch, fp32) + sinusoidal PE gating.
//   coords: (B,2) fp32   grids: (513*513, 24) fp32   out: (B,24) fp32
// Warp-aligned cooperative layout, 3 points per thread for MLP=12:
// warp owns 15 points; lane l<30 -> role j=l%6 (channels 4j..4j+3), local
// q=l/6; handles points warp*15+q, +5, +10. All 12 gathers issued before
// any use. Trig: 2 MUFU per point + double-angle chain.

#define GRID_ELEMS (513 * 513 * 24)
#define TWO_PI_F 6.28318530717958647692f
#define PI_F     3.14159265358979323846f

__device__ __forceinline__ void lpe_compute(
    float lu, float lv, int j,
    const float4& a, const float4& bq, const float4& cq, const float4& dq,
    float4& o)
{
    // PE gates. Lane roles: j=0,1 base (gate 1);
    // j=2: cos(2^k*2pi*lu)  j=3: sin(..lu)  j=4: cos(..lv)  j=5: sin(..lv)
    float l = (j < 4) ? lu : lv;
    float ang = fmaf(l, TWO_PI_F, -PI_F);        // [-pi, pi)
    float s0 = -__sinf(ang);                     // sin(2*pi*l)
    float c0 = -__cosf(ang);                     // cos(2*pi*l)
    float s1 = 2.0f * s0 * c0;
    float c1 = fmaf(2.0f * c0, c0, -1.0f);
    float s2 = 2.0f * s1 * c1;
    float c2 = fmaf(2.0f * c1, c1, -1.0f);
    float s3 = 2.0f * s2 * c2;
    float c3 = fmaf(2.0f * c2, c2, -1.0f);

    bool use_sin = (j & 1);
    float pe0 = use_sin ? s0 : c0;
    float pe1 = use_sin ? s1 : c1;
    float pe2 = use_sin ? s2 : c2;
    float pe3 = use_sin ? s3 : c3;
    if (j < 2) { pe0 = 1.0f; pe1 = 1.0f; pe2 = 1.0f; pe3 = 1.0f; }

    float wu0 = 1.0f - lu, wv0 = 1.0f - lv;

    float t0, b0;
    t0 = a.x * wu0 + bq.x * lu;  b0 = cq.x * wu0 + dq.x * lu;
    o.x = __half2float(__float2half_rn((t0 * wv0 + b0 * lv) * pe0));
    t0 = a.y * wu0 + bq.y * lu;  b0 = cq.y * wu0 + dq.y * lu;
    o.y = __half2float(__float2half_rn((t0 * wv0 + b0 * lv) * pe1));
    t0 = a.z * wu0 + bq.z * lu;  b0 = cq.z * wu0 + dq.z * lu;
    o.z = __half2float(__float2half_rn((t0 * wv0 + b0 * lv) * pe2));
    t0 = a.w * wu0 + bq.w * lu;  b0 = cq.w * wu0 + dq.w * lu;
    o.w = __half2float(__float2half_rn((t0 * wv0 + b0 * lv) * pe3));
}

__device__ __forceinline__ void setup_point(
    const float2& c, float& lu, float& lv, int& idx00)
{
    float u = fminf(fmaxf(c.x, 0.0f), 1.0f - 1e-6f);
    float v = fminf(fmaxf(c.y, 0.0f), 1.0f - 1e-6f);
    float fu = u * 512.0f;
    float fv = v * 512.0f;
    int iu = (int)fu; iu = iu > 511 ? 511 : iu;
    int iv = (int)fv; iv = iv > 511 ? 511 : iv;
    lu = fu - (float)iu;
    lv = fv - (float)iv;
    idx00 = iu + iv * 513;
}

__global__ __launch_bounds__(256) void lpe2d_kernel(
    const float2* __restrict__ coords,
    const float4* __restrict__ grids,   // grid row = 6 float4 (24 floats)
    float4*       __restrict__ out,     // out row  = 6 float4 (24 floats)
    int B)
{
    int gwarp = (blockIdx.x * blockDim.x + threadIdx.x) >> 5;
    int lane  = threadIdx.x & 31;
    if (lane >= 30) return;             // 2 idle lanes per warp (no straddle)
    int q = lane / 6;                   // local point 0..4
    int j = lane - q * 6;               // chunk role 0..5

    int p0 = gwarp * 15 + q;
    int p1 = p0 + 5;
    int p2 = p0 + 10;
    if (p0 >= B) return;
    bool has1 = (p1 < B);
    bool has2 = (p2 < B);

    // Coord loads (broadcast within each 6-lane group); clamp to keep
    // addresses valid without divergence.
    float2 c0 = coords[p0];
    float2 c1 = coords[has1 ? p1 : p0];
    float2 c2 = coords[has2 ? p2 : p0];

    float lu0, lv0, lu1, lv1, lu2, lv2;
    int i0, i1, i2;
    setup_point(c0, lu0, lv0, i0);
    setup_point(c1, lu1, lv1, i1);
    setup_point(c2, lu2, lv2, i2);

    const float4* r00 = grids + (size_t)i0 * 6;
    const float4* r01 = grids + (size_t)(i0 + 513) * 6;
    const float4* r10 = grids + (size_t)i1 * 6;
    const float4* r11 = grids + (size_t)(i1 + 513) * 6;
    const float4* r20 = grids + (size_t)i2 * 6;
    const float4* r21 = grids + (size_t)(i2 + 513) * 6;

    // Issue all 12 gathers before any use (MLP=12).
    float4 a0 = r00[j];
    float4 b0 = r00[j + 6];
    float4 g0 = r01[j];
    float4 d0 = r01[j + 6];
    float4 a1 = r10[j];
    float4 b1 = r10[j + 6];
    float4 g1 = r11[j];
    float4 d1 = r11[j + 6];
    float4 a2 = r20[j];
    float4 b2 = r20[j + 6];
    float4 g2 = r21[j];
    float4 d2 = r21[j + 6];

    // Consume in issue order (earliest loads first).
    float4 o0;
    lpe_compute(lu0, lv0, j, a0, b0, g0, d0, o0);
    __stcs(out + (size_t)p0 * 6 + j, o0);

    float4 o1;
    lpe_compute(lu1, lv1, j, a1, b1, g1, d1, o1);
    if (has1) __stcs(out + (size_t)p1 * 6 + j, o1);

    float4 o2;
    lpe_compute(lu2, lv2, j, a2, b2, g2, d2, o2);
    if (has2) __stcs(out + (size_t)p2 * 6 + j, o2);
}

extern "C" void kernel_launch(void* const* d_in, const int* in_sizes, int n_in,
                              void* d_out, int out_size) {
    // Bind inputs by size: grids has exactly 513*513*24 elements.
    int gi = -1, ci = -1;
    for (int i = 0; i < n_in; i++)
        if (in_sizes[i] == GRID_ELEMS && gi < 0) gi = i;
    for (int i = 0; i < n_in; i++)
        if (i != gi && ci < 0) ci = i;
    if (gi < 0) { gi = 1; ci = 0; }

    const float2* coords = (const float2*)d_in[ci];
    const float4* grids  = (const float4*)d_in[gi];
    float4*       out    = (float4*)d_out;
    int B = out_size / 24;                          // out is (B, 24) fp32
    long long warps = ((long long)B + 14) / 15;     // 15 points per warp
    long long threads_total = warps * 32;
    int threads = 256;
    int blocks = (int)((threads_total + threads - 1) / threads);
    lpe2d_kernel<<<blocks, threads>>>(coords, grids, out, B);
}